// round 15
// baseline (speedup 1.0000x reference)
#include <cuda_runtime.h>
#include <cuda_fp16.h>
#include <cstdint>

namespace {

// smem word offsets (fp16 tiles: 64 rows x 32 fp16, stride 20 words)
constexpr int QH = 0;
constexpr int QL = 1280;
constexpr int KH = 2560;
constexpr int VP = 3840;
constexpr int BI = 5120;    // bias: 8 heads x 228 words
constexpr int SMW = 5120 + 8 * 228;   // 6944 words = 27776 bytes

__device__ __forceinline__ uint32_t packf16(float lo, float hi) {
    uint32_t d;
    asm("cvt.rn.f16x2.f32 %0, %1, %2;" : "=r"(d) : "f"(hi), "f"(lo));
    return d;
}
__device__ __forceinline__ uint32_t smem_u32(const void* p) {
    uint32_t a;
    asm("{ .reg .u64 t; cvta.to.shared.u64 t, %1; cvt.u32.u64 %0, t; }" : "=r"(a) : "l"(p));
    return a;
}
__device__ __forceinline__ void mma16(float* c, const uint32_t* a, uint32_t b0, uint32_t b1) {
    asm volatile("mma.sync.aligned.m16n8k16.row.col.f32.f16.f16.f32 "
        "{%0,%1,%2,%3}, {%4,%5,%6,%7}, {%8,%9}, {%0,%1,%2,%3};"
        : "+f"(c[0]), "+f"(c[1]), "+f"(c[2]), "+f"(c[3])
        : "r"(a[0]), "r"(a[1]), "r"(a[2]), "r"(a[3]), "r"(b0), "r"(b1));
}
__device__ __forceinline__ void ldsm4(uint32_t* r, uint32_t addr) {
    asm volatile("ldmatrix.sync.aligned.m8n8.x4.shared.b16 {%0,%1,%2,%3}, [%4];"
        : "=r"(r[0]), "=r"(r[1]), "=r"(r[2]), "=r"(r[3]) : "r"(addr));
}
__device__ __forceinline__ void ldsm4t(uint32_t* r, uint32_t addr) {
    asm volatile("ldmatrix.sync.aligned.m8n8.x4.trans.shared.b16 {%0,%1,%2,%3}, [%4];"
        : "=r"(r[0]), "=r"(r[1]), "=r"(r[2]), "=r"(r[3]) : "r"(addr));
}
__device__ __forceinline__ void h2split(float x, float y, uint32_t& hi, uint32_t& lo) {
    __half hx = __float2half_rn(x), hy = __float2half_rn(y);
    float rx = x - __half2float(hx), ry = y - __half2float(hy);
    hi = packf16(x, y);
    lo = packf16(rx, ry);
}

__global__ __launch_bounds__(128, 4)
void swin_mma_kernel(const float* __restrict__ gq, const float* __restrict__ gk,
                     const float* __restrict__ gv, const float* __restrict__ gbias,
                     float* __restrict__ gout)
{
    __shared__ uint32_t SM[SMW];

    const int tid   = threadIdx.x;
    const int head0 = (blockIdx.x & 1) << 3;    // 8 heads per CTA
    const int wy    = blockIdx.x >> 1;
    const int b     = wy >> 6;
    const int win   = wy & 63;
    const int win_h = win >> 3, win_w = win & 7;
    const float scale = 0.17677669529663687f;   // 1/sqrt(32)

    // ---- prologue: this CTA's 8 bias head-slices -> smem [hh][idx] ----
    {
        float* bsm = reinterpret_cast<float*>(SM) + BI;
        for (int t = tid; t < 1800; t += 128) {
            int idx = t >> 3, hh = t & 7;
            bsm[hh * 228 + idx] = gbias[idx * 16 + head0 + hh];
        }
    }

    // ---- head-independent gather bases (cyclic shift -4 folded in) ----
    int tokbase[4];
    #pragma unroll
    for (int r = 0; r < 4; ++r) {
        int u = tid + (r << 7);
        int t = u >> 3, cq = u & 7;
        int sh  = ((win_h << 3) + (t >> 3) + 4) & 63;
        int sw2 = ((win_w << 3) + (t & 7) + 4) & 63;
        tokbase[r] = ((((b << 6) + sh) << 6) + sw2) * 512 + (cq << 2);
    }

    // ---- prefetch head0, convert to packed fp16 staging ----
    uint2 qhS[4], qlS[4], khS[4], vS[4];
    #pragma unroll
    for (int r = 0; r < 4; ++r) {
        int gb = tokbase[r] + head0 * 32;
        float4 q = *reinterpret_cast<const float4*>(gq + gb);
        float4 k = *reinterpret_cast<const float4*>(gk + gb);
        float4 v = *reinterpret_cast<const float4*>(gv + gb);
        h2split(q.x * scale, q.y * scale, qhS[r].x, qlS[r].x);
        h2split(q.z * scale, q.w * scale, qhS[r].y, qlS[r].y);
        khS[r] = make_uint2(packf16(k.x, k.y), packf16(k.z, k.w));
        vS[r]  = make_uint2(packf16(v.x, v.y), packf16(v.z, v.w));
    }

    // ---- hoisted lane constants ----
    const int w    = tid >> 5;
    const int lane = tid & 31;
    const int g    = lane >> 2;
    const int t4   = lane & 3;
    const int l7   = lane & 7;
    const int m0   = w << 4;
    const int iA   = m0 + g;
    const int iB   = m0 + g + 8;

    const uint32_t smb = smem_u32(SM);
    const uint32_t aHb = smb + (uint32_t)((QH + (m0 + (((lane >> 3) & 1) << 3) + l7) * 20) << 2)
                       + (uint32_t)((lane >> 4) << 4);
    const uint32_t aLb = aHb + (uint32_t)((QL - QH) << 2);
    uint32_t bKb[4];
    #pragma unroll
    for (int mm = 0; mm < 4; ++mm)
        bKb[mm] = smb + (uint32_t)((KH + ((mm << 4) + (((lane >> 4) & 1) << 3) + l7) * 20) << 2)
                + (uint32_t)(((lane >> 3) & 1) << 4);

    const bool wh7 = (win_h == 7), ww7 = (win_w == 7);
    const bool hA4 = ((iA >> 3) >= 4), hB4 = ((iB >> 3) >= 4);
    const bool wA4 = ((iA & 7) >= 4),  wB4 = ((iB & 7) >= 4);
    const bool jw4 = (t4 >= 2);
    const int bA = 15 * (iA >> 3) + (iA & 7) + 112;
    const int bB = 15 * (iB >> 3) + (iB & 7) + 112;
    const int tokrow = l7 + (((lane >> 3) & 1) << 3);
    const int chanw  = (lane >> 4) << 2;
    const int ohA = ((win_h << 3) + (iA >> 3) + 4) & 63;
    const int owA = ((win_w << 3) + (iA & 7) + 4) & 63;
    const int ohB = ((win_h << 3) + (iB >> 3) + 4) & 63;
    const int owB = ((win_w << 3) + (iB & 7) + 4) & 63;
    const int dAb = ((((b << 6) + ohA) << 6) + owA) * 512 + (t4 << 1);
    const int dBb = ((((b << 6) + ohB) << 6) + owB) * 512 + (t4 << 1);

    for (int h = 0; h < 8; ++h) {
        const int head = head0 + h;
        __syncthreads();   // previous iteration's smem readers done

        // ---- staged fp16 -> smem ----
        #pragma unroll
        for (int r = 0; r < 4; ++r) {
            int u = tid + (r << 7);
            int t = u >> 3, cq = u & 7;
            int o20 = t * 20 + (cq << 1);
            *reinterpret_cast<uint2*>(&SM[QH + o20]) = qhS[r];
            *reinterpret_cast<uint2*>(&SM[QL + o20]) = qlS[r];
            *reinterpret_cast<uint2*>(&SM[KH + o20]) = khS[r];
            *reinterpret_cast<uint2*>(&SM[VP + o20]) = vS[r];
        }

        // ---- prefetch + convert next head (hidden under this head's compute) ----
        if (h < 7) {
            #pragma unroll
            for (int r = 0; r < 4; ++r) {
                int gb = tokbase[r] + (head + 1) * 32;
                float4 q = *reinterpret_cast<const float4*>(gq + gb);
                float4 k = *reinterpret_cast<const float4*>(gk + gb);
                float4 v = *reinterpret_cast<const float4*>(gv + gb);
                h2split(q.x * scale, q.y * scale, qhS[r].x, qlS[r].x);
                h2split(q.z * scale, q.w * scale, qhS[r].y, qlS[r].y);
                khS[r] = make_uint2(packf16(k.x, k.y), packf16(k.z, k.w));
                vS[r]  = make_uint2(packf16(v.x, v.y), packf16(v.z, v.w));
            }
        }
        __syncthreads();

        // ---- QK: 2xFP16 (qh*k + ql*k), m16n8k16, LDSM-fed ----
        float c[8][4] = {};
        #pragma unroll
        for (int kc = 0; kc < 2; ++kc) {
            uint32_t ah[4], al[4];
            ldsm4(ah, aHb + (uint32_t)(kc << 5));
            ldsm4(al, aLb + (uint32_t)(kc << 5));
            #pragma unroll
            for (int mm = 0; mm < 4; ++mm) {
                uint32_t bb[4];
                ldsm4(bb, bKb[mm] + (uint32_t)(kc << 5));
                float* c0 = c[2 * mm];
                float* c1 = c[2 * mm + 1];
                mma16(c0, ah, bb[0], bb[1]);
                mma16(c0, al, bb[0], bb[1]);
                mma16(c1, ah, bb[2], bb[3]);
                mma16(c1, al, bb[2], bb[3]);
            }
        }

        // ---- bias + analytic shift-mask + softmax (no max subtraction:
        //      logits are O(1); mask of -100 underflows exp to 0 exactly as intended) ----
        const float* bias = reinterpret_cast<const float*>(SM) + BI + h * 228;
        float sA = 0.0f, sB = 0.0f;
        #pragma unroll
        for (int nt = 0; nt < 8; ++nt) {
            const bool jh4 = (nt >= 4);
            const float subA = ((wh7 && (hA4 != jh4)) || (ww7 && (wA4 != jw4))) ? 100.0f : 0.0f;
            const float subB = ((wh7 && (hB4 != jh4)) || (ww7 && (wB4 != jw4))) ? 100.0f : 0.0f;
            #pragma unroll
            for (int q = 0; q < 2; ++q) {
                int bj = 15 * nt + (t4 << 1) + q;
                float pA = __expf(c[nt][q]     + bias[bA - bj] - subA);
                float pB = __expf(c[nt][2 + q] + bias[bB - bj] - subB);
                c[nt][q] = pA; c[nt][2 + q] = pB;
                sA += pA; sB += pB;
            }
        }
        sA += __shfl_xor_sync(0xffffffffu, sA, 1);
        sA += __shfl_xor_sync(0xffffffffu, sA, 2);
        sB += __shfl_xor_sync(0xffffffffu, sB, 1);
        sB += __shfl_xor_sync(0xffffffffu, sB, 2);
        const float invA = 1.0f / sA, invB = 1.0f / sB;

        // ---- PV: P in registers (acc frag == fp16 A frag); V via ldsm.trans ----
        float o[4][4] = {};
        #pragma unroll
        for (int ck = 0; ck < 4; ++ck) {
            uint32_t aF[4];
            aF[0] = packf16(c[2 * ck][0] * invA,     c[2 * ck][1] * invA);
            aF[1] = packf16(c[2 * ck][2] * invB,     c[2 * ck][3] * invB);
            aF[2] = packf16(c[2 * ck + 1][0] * invA, c[2 * ck + 1][1] * invA);
            aF[3] = packf16(c[2 * ck + 1][2] * invB, c[2 * ck + 1][3] * invB);
            uint32_t vrow = smb + (uint32_t)((VP + ((ck << 4) + tokrow) * 20 + chanw) << 2);
            #pragma unroll
            for (int nb = 0; nb < 2; ++nb) {
                uint32_t bv[4];
                ldsm4t(bv, vrow + (uint32_t)(nb << 5));
                mma16(o[2 * nb],     aF, bv[0], bv[1]);
                mma16(o[2 * nb + 1], aF, bv[2], bv[3]);
            }
        }

        // ---- store ----
        float* dA = gout + dAb + head * 32;
        float* dB = gout + dBb + head * 32;
        #pragma unroll
        for (int nt = 0; nt < 4; ++nt) {
            *reinterpret_cast<float2*>(dA + (nt << 3)) = make_float2(o[nt][0], o[nt][1]);
            *reinterpret_cast<float2*>(dB + (nt << 3)) = make_float2(o[nt][2], o[nt][3]);
        }
    }
}

}  // namespace

extern "C" void kernel_launch(void* const* d_in, const int* in_sizes, int n_in,
                              void* d_out, int out_size)
{
    (void)in_sizes; (void)n_in; (void)out_size;
    const float* q    = (const float*)d_in[0];
    const float* k    = (const float*)d_in[1];
    const float* v    = (const float*)d_in[2];
    const float* bias = (const float*)d_in[3];
    // 1024 windows x 2 head-octets = 2048 CTAs, 8 heads each
    swin_mma_kernel<<<2048, 128>>>(q, k, v, bias, (float*)d_out);
}

// round 16
// speedup vs baseline: 1.0997x; 1.0997x over previous
#include <cuda_runtime.h>
#include <cuda_fp16.h>
#include <cstdint>

namespace {

// smem word offsets (fp16 tiles: 64 rows x 32 fp16, stride 20 words)
constexpr int QH = 0;
constexpr int QL = 1280;
constexpr int KH = 2560;
constexpr int VP = 3840;
constexpr int BI = 5120;    // bias, 225 floats
constexpr int SMW = 5346;   // 21384 bytes

__device__ __forceinline__ uint32_t packf16(float lo, float hi) {
    uint32_t d;
    asm("cvt.rn.f16x2.f32 %0, %1, %2;" : "=r"(d) : "f"(hi), "f"(lo));
    return d;
}
__device__ __forceinline__ uint32_t smem_u32(const void* p) {
    uint32_t a;
    asm("{ .reg .u64 t; cvta.to.shared.u64 t, %1; cvt.u32.u64 %0, t; }" : "=r"(a) : "l"(p));
    return a;
}
__device__ __forceinline__ void mma16(float* c, const uint32_t* a, uint32_t b0, uint32_t b1) {
    asm volatile("mma.sync.aligned.m16n8k16.row.col.f32.f16.f16.f32 "
        "{%0,%1,%2,%3}, {%4,%5,%6,%7}, {%8,%9}, {%0,%1,%2,%3};"
        : "+f"(c[0]), "+f"(c[1]), "+f"(c[2]), "+f"(c[3])
        : "r"(a[0]), "r"(a[1]), "r"(a[2]), "r"(a[3]), "r"(b0), "r"(b1));
}
__device__ __forceinline__ void ldsm4(uint32_t* r, uint32_t addr) {
    asm volatile("ldmatrix.sync.aligned.m8n8.x4.shared.b16 {%0,%1,%2,%3}, [%4];"
        : "=r"(r[0]), "=r"(r[1]), "=r"(r[2]), "=r"(r[3]) : "r"(addr));
}
__device__ __forceinline__ void ldsm4t(uint32_t* r, uint32_t addr) {
    asm volatile("ldmatrix.sync.aligned.m8n8.x4.trans.shared.b16 {%0,%1,%2,%3}, [%4];"
        : "=r"(r[0]), "=r"(r[1]), "=r"(r[2]), "=r"(r[3]) : "r"(addr));
}
__device__ __forceinline__ void h2split(float x, float y, uint32_t& hi, uint32_t& lo) {
    __half hx = __float2half_rn(x), hy = __float2half_rn(y);
    float rx = x - __half2float(hx), ry = y - __half2float(hy);
    hi = packf16(x, y);
    lo = packf16(rx, ry);
}

__global__ __launch_bounds__(128, 5)
void swin_mma_kernel(const float* __restrict__ gq, const float* __restrict__ gk,
                     const float* __restrict__ gv, const float* __restrict__ gbias,
                     float* __restrict__ gout)
{
    __shared__ uint32_t SM[SMW];

    const int tid   = threadIdx.x;
    const int head0 = (blockIdx.x & 1) << 3;    // 8 heads per CTA
    const int wy    = blockIdx.x >> 1;
    const int b     = wy >> 6;
    const int win   = wy & 63;
    const int win_h = win >> 3, win_w = win & 7;
    const float scale = 0.17677669529663687f;   // 1/sqrt(32)

    // ---- head-independent gather bases (cyclic shift -4 folded in) ----
    int tokbase[4];
    #pragma unroll
    for (int r = 0; r < 4; ++r) {
        int u = tid + (r << 7);
        int t = u >> 3, cq = u & 7;
        int sh  = ((win_h << 3) + (t >> 3) + 4) & 63;
        int sw2 = ((win_w << 3) + (t & 7) + 4) & 63;
        tokbase[r] = ((((b << 6) + sh) << 6) + sw2) * 512 + (cq << 2);
    }

    // ---- prefetch head0, convert to packed fp16 staging ----
    uint2 qhS[4], qlS[4], khS[4], vS[4];
    float bs0, bs1 = 0.0f;
    #pragma unroll
    for (int r = 0; r < 4; ++r) {
        int gb = tokbase[r] + head0 * 32;
        float4 q = *reinterpret_cast<const float4*>(gq + gb);
        float4 k = *reinterpret_cast<const float4*>(gk + gb);
        float4 v = *reinterpret_cast<const float4*>(gv + gb);
        h2split(q.x * scale, q.y * scale, qhS[r].x, qlS[r].x);
        h2split(q.z * scale, q.w * scale, qhS[r].y, qlS[r].y);
        khS[r] = make_uint2(packf16(k.x, k.y), packf16(k.z, k.w));
        vS[r]  = make_uint2(packf16(v.x, v.y), packf16(v.z, v.w));
    }
    bs0 = gbias[tid * 16 + head0];
    if (tid < 97) bs1 = gbias[(tid + 128) * 16 + head0];

    // ---- hoisted lane constants ----
    const int w    = tid >> 5;
    const int lane = tid & 31;
    const int g    = lane >> 2;
    const int t4   = lane & 3;
    const int l7   = lane & 7;
    const int m0   = w << 4;
    const int iA   = m0 + g;
    const int iB   = m0 + g + 8;

    const uint32_t smb = smem_u32(SM);
    const uint32_t aHb = smb + (uint32_t)((QH + (m0 + (((lane >> 3) & 1) << 3) + l7) * 20) << 2)
                       + (uint32_t)((lane >> 4) << 4);
    const uint32_t aLb = aHb + (uint32_t)((QL - QH) << 2);
    // single B base; per-16-token group offset is linear: +1280 B
    const uint32_t bKb0 = smb + (uint32_t)((KH + ((((lane >> 4) & 1) << 3) + l7) * 20) << 2)
                        + (uint32_t)(((lane >> 3) & 1) << 4);

    const bool wh7 = (win_h == 7), ww7 = (win_w == 7);
    const bool hA4 = ((iA >> 3) >= 4), hB4 = ((iB >> 3) >= 4);
    const bool wA4 = ((iA & 7) >= 4),  wB4 = ((iB & 7) >= 4);
    const bool jw4 = (t4 >= 2);
    const int bA = 15 * (iA >> 3) + (iA & 7) + 112;
    const int bB = 15 * (iB >> 3) + (iB & 7) + 112;
    const int tokrow = l7 + (((lane >> 3) & 1) << 3);
    const int chanw  = (lane >> 4) << 2;
    const int ohA = ((win_h << 3) + (iA >> 3) + 4) & 63;
    const int owA = ((win_w << 3) + (iA & 7) + 4) & 63;
    const int ohB = ((win_h << 3) + (iB >> 3) + 4) & 63;
    const int owB = ((win_w << 3) + (iB & 7) + 4) & 63;
    const int dAb = ((((b << 6) + ohA) << 6) + owA) * 512 + (t4 << 1);
    const int dBb = ((((b << 6) + ohB) << 6) + owB) * 512 + (t4 << 1);

    for (int h = 0; h < 8; ++h) {
        const int head = head0 + h;
        __syncthreads();   // previous iteration's smem readers done

        // ---- staged fp16 -> smem ----
        #pragma unroll
        for (int r = 0; r < 4; ++r) {
            int u = tid + (r << 7);
            int t = u >> 3, cq = u & 7;
            int o20 = t * 20 + (cq << 1);
            *reinterpret_cast<uint2*>(&SM[QH + o20]) = qhS[r];
            *reinterpret_cast<uint2*>(&SM[QL + o20]) = qlS[r];
            *reinterpret_cast<uint2*>(&SM[KH + o20]) = khS[r];
            *reinterpret_cast<uint2*>(&SM[VP + o20]) = vS[r];
        }
        reinterpret_cast<float*>(SM)[BI + tid] = bs0;
        if (tid < 97) reinterpret_cast<float*>(SM)[BI + 128 + tid] = bs1;

        // ---- prefetch + convert next head (hidden under this head's compute) ----
        if (h < 7) {
            #pragma unroll
            for (int r = 0; r < 4; ++r) {
                int gb = tokbase[r] + (head + 1) * 32;
                float4 q = *reinterpret_cast<const float4*>(gq + gb);
                float4 k = *reinterpret_cast<const float4*>(gk + gb);
                float4 v = *reinterpret_cast<const float4*>(gv + gb);
                h2split(q.x * scale, q.y * scale, qhS[r].x, qlS[r].x);
                h2split(q.z * scale, q.w * scale, qhS[r].y, qlS[r].y);
                khS[r] = make_uint2(packf16(k.x, k.y), packf16(k.z, k.w));
                vS[r]  = make_uint2(packf16(v.x, v.y), packf16(v.z, v.w));
            }
            bs0 = gbias[tid * 16 + head + 1];
            if (tid < 97) bs1 = gbias[(tid + 128) * 16 + head + 1];
        }
        __syncthreads();

        // ---- QK: 2xFP16 (qh*k + ql*k), m16n8k16, LDSM-fed ----
        float c[8][4] = {};
        #pragma unroll
        for (int kc = 0; kc < 2; ++kc) {
            uint32_t ah[4], al[4];
            ldsm4(ah, aHb + (uint32_t)(kc << 5));
            ldsm4(al, aLb + (uint32_t)(kc << 5));
            #pragma unroll
            for (int mm = 0; mm < 4; ++mm) {
                uint32_t bb[4];
                ldsm4(bb, bKb0 + (uint32_t)(mm * 1280) + (uint32_t)(kc << 5));
                float* c0 = c[2 * mm];
                float* c1 = c[2 * mm + 1];
                mma16(c0, ah, bb[0], bb[1]);
                mma16(c0, al, bb[0], bb[1]);
                mma16(c1, ah, bb[2], bb[3]);
                mma16(c1, al, bb[2], bb[3]);
            }
        }

        // ---- bias + analytic shift-mask + softmax ----
        const float* bias = reinterpret_cast<const float*>(SM) + BI;
        float mA = -1e30f, mB = -1e30f;
        #pragma unroll
        for (int nt = 0; nt < 8; ++nt) {
            const bool jh4 = (nt >= 4);
            const float subA = ((wh7 && (hA4 != jh4)) || (ww7 && (wA4 != jw4))) ? 100.0f : 0.0f;
            const float subB = ((wh7 && (hB4 != jh4)) || (ww7 && (wB4 != jw4))) ? 100.0f : 0.0f;
            #pragma unroll
            for (int q = 0; q < 2; ++q) {
                int bj = 15 * nt + (t4 << 1) + q;
                float xA = c[nt][q]     + bias[bA - bj] - subA;
                float xB = c[nt][2 + q] + bias[bB - bj] - subB;
                c[nt][q] = xA; c[nt][2 + q] = xB;
                mA = fmaxf(mA, xA); mB = fmaxf(mB, xB);
            }
        }
        mA = fmaxf(mA, __shfl_xor_sync(0xffffffffu, mA, 1));
        mA = fmaxf(mA, __shfl_xor_sync(0xffffffffu, mA, 2));
        mB = fmaxf(mB, __shfl_xor_sync(0xffffffffu, mB, 1));
        mB = fmaxf(mB, __shfl_xor_sync(0xffffffffu, mB, 2));
        float sA = 0.0f, sB = 0.0f;
        #pragma unroll
        for (int nt = 0; nt < 8; ++nt) {
            #pragma unroll
            for (int q = 0; q < 2; ++q) {
                float pA = __expf(c[nt][q] - mA);
                float pB = __expf(c[nt][2 + q] - mB);
                c[nt][q] = pA; c[nt][2 + q] = pB;
                sA += pA; sB += pB;
            }
        }
        sA += __shfl_xor_sync(0xffffffffu, sA, 1);
        sA += __shfl_xor_sync(0xffffffffu, sA, 2);
        sB += __shfl_xor_sync(0xffffffffu, sB, 1);
        sB += __shfl_xor_sync(0xffffffffu, sB, 2);
        const float invA = 1.0f / sA, invB = 1.0f / sB;

        // ---- PV: P in registers (acc frag == fp16 A frag); V via ldsm.trans ----
        float o[4][4] = {};
        #pragma unroll
        for (int ck = 0; ck < 4; ++ck) {
            uint32_t aF[4];
            aF[0] = packf16(c[2 * ck][0] * invA,     c[2 * ck][1] * invA);
            aF[1] = packf16(c[2 * ck][2] * invB,     c[2 * ck][3] * invB);
            aF[2] = packf16(c[2 * ck + 1][0] * invA, c[2 * ck + 1][1] * invA);
            aF[3] = packf16(c[2 * ck + 1][2] * invB, c[2 * ck + 1][3] * invB);
            uint32_t vrow = smb + (uint32_t)((VP + ((ck << 4) + tokrow) * 20 + chanw) << 2);
            #pragma unroll
            for (int nb = 0; nb < 2; ++nb) {
                uint32_t bv[4];
                ldsm4t(bv, vrow + (uint32_t)(nb << 5));
                mma16(o[2 * nb],     aF, bv[0], bv[1]);
                mma16(o[2 * nb + 1], aF, bv[2], bv[3]);
            }
        }

        // ---- store ----
        float* dA = gout + dAb + head * 32;
        float* dB = gout + dBb + head * 32;
        #pragma unroll
        for (int nt = 0; nt < 4; ++nt) {
            *reinterpret_cast<float2*>(dA + (nt << 3)) = make_float2(o[nt][0], o[nt][1]);
            *reinterpret_cast<float2*>(dB + (nt << 3)) = make_float2(o[nt][2], o[nt][3]);
        }
    }
}

}  // namespace

extern "C" void kernel_launch(void* const* d_in, const int* in_sizes, int n_in,
                              void* d_out, int out_size)
{
    (void)in_sizes; (void)n_in; (void)out_size;
    const float* q    = (const float*)d_in[0];
    const float* k    = (const float*)d_in[1];
    const float* v    = (const float*)d_in[2];
    const float* bias = (const float*)d_in[3];
    // 1024 windows x 2 head-octets = 2048 CTAs, 8 heads each
    swin_mma_kernel<<<2048, 128>>>(q, k, v, bias, (float*)d_out);
}

// round 17
// speedup vs baseline: 1.1879x; 1.0802x over previous
#include <cuda_runtime.h>
#include <cuda_fp16.h>
#include <cstdint>

namespace {

// smem word offsets (fp16 tiles: 64 rows x 32 fp16, stride 20 words)
constexpr int KH = 0;
constexpr int VP = 1280;
constexpr int BI = 2560;    // bias, 225 floats
constexpr int SMW = 2786;   // 11144 bytes

__device__ __forceinline__ uint32_t packf16(float lo, float hi) {
    uint32_t d;
    asm("cvt.rn.f16x2.f32 %0, %1, %2;" : "=r"(d) : "f"(hi), "f"(lo));
    return d;
}
__device__ __forceinline__ uint32_t smem_u32(const void* p) {
    uint32_t a;
    asm("{ .reg .u64 t; cvta.to.shared.u64 t, %1; cvt.u32.u64 %0, t; }" : "=r"(a) : "l"(p));
    return a;
}
__device__ __forceinline__ void mma16(float* c, const uint32_t* a, uint32_t b0, uint32_t b1) {
    asm volatile("mma.sync.aligned.m16n8k16.row.col.f32.f16.f16.f32 "
        "{%0,%1,%2,%3}, {%4,%5,%6,%7}, {%8,%9}, {%0,%1,%2,%3};"
        : "+f"(c[0]), "+f"(c[1]), "+f"(c[2]), "+f"(c[3])
        : "r"(a[0]), "r"(a[1]), "r"(a[2]), "r"(a[3]), "r"(b0), "r"(b1));
}
__device__ __forceinline__ void ldsm4(uint32_t* r, uint32_t addr) {
    asm volatile("ldmatrix.sync.aligned.m8n8.x4.shared.b16 {%0,%1,%2,%3}, [%4];"
        : "=r"(r[0]), "=r"(r[1]), "=r"(r[2]), "=r"(r[3]) : "r"(addr));
}
__device__ __forceinline__ void ldsm4t(uint32_t* r, uint32_t addr) {
    asm volatile("ldmatrix.sync.aligned.m8n8.x4.trans.shared.b16 {%0,%1,%2,%3}, [%4];"
        : "=r"(r[0]), "=r"(r[1]), "=r"(r[2]), "=r"(r[3]) : "r"(addr));
}
// split packed pair into fp16 hi + fp16 lo (residual)
__device__ __forceinline__ void h2split(float x, float y, uint32_t& hi, uint32_t& lo) {
    __half hx = __float2half_rn(x), hy = __float2half_rn(y);
    float rx = x - __half2float(hx), ry = y - __half2float(hy);
    hi = packf16(x, y);
    lo = packf16(rx, ry);
}

__global__ __launch_bounds__(128, 5)
void swin_mma_kernel(const float* __restrict__ gq, const float* __restrict__ gk,
                     const float* __restrict__ gv, const float* __restrict__ gbias,
                     float* __restrict__ gout)
{
    __shared__ uint32_t SM[SMW];

    const int tid   = threadIdx.x;
    const int head0 = (blockIdx.x & 1) << 3;    // 8 heads per CTA
    const int wy    = blockIdx.x >> 1;
    const int b     = wy >> 6;
    const int win   = wy & 63;
    const int win_h = win >> 3, win_w = win & 7;
    const float scale = 0.17677669529663687f;   // 1/sqrt(32)

    // ---- head-independent gather bases (cyclic shift -4 folded in) for K/V staging ----
    int tokbase[4];
    #pragma unroll
    for (int r = 0; r < 4; ++r) {
        int u = tid + (r << 7);
        int t = u >> 3, cq = u & 7;
        int sh  = ((win_h << 3) + (t >> 3) + 4) & 63;
        int sw2 = ((win_w << 3) + (t & 7) + 4) & 63;
        tokbase[r] = ((((b << 6) + sh) << 6) + sw2) * 512 + (cq << 2);
    }

    // ---- lane constants ----
    const int w    = tid >> 5;
    const int lane = tid & 31;
    const int g    = lane >> 2;
    const int t4   = lane & 3;
    const int l7   = lane & 7;
    const int m0   = w << 4;
    const int iA   = m0 + g;
    const int iB   = m0 + g + 8;

    // Q direct-load row bases (head-independent; +2*t4 column offset folded)
    const int shA = ((win_h << 3) + (iA >> 3) + 4) & 63;
    const int swA = ((win_w << 3) + (iA & 7) + 4) & 63;
    const int shB = ((win_h << 3) + (iB >> 3) + 4) & 63;
    const int swB = ((win_w << 3) + (iB & 7) + 4) & 63;
    const int qbaseA = ((((b << 6) + shA) << 6) + swA) * 512 + (t4 << 1);
    const int qbaseB = ((((b << 6) + shB) << 6) + swB) * 512 + (t4 << 1);

    // ---- prefetch head0 K/V, convert to packed fp16 staging ----
    uint2 khS[4], vS[4];
    float bs0, bs1 = 0.0f;
    #pragma unroll
    for (int r = 0; r < 4; ++r) {
        int gb = tokbase[r] + head0 * 32;
        float4 k = *reinterpret_cast<const float4*>(gk + gb);
        float4 v = *reinterpret_cast<const float4*>(gv + gb);
        khS[r] = make_uint2(packf16(k.x, k.y), packf16(k.z, k.w));
        vS[r]  = make_uint2(packf16(v.x, v.y), packf16(v.z, v.w));
    }
    bs0 = gbias[tid * 16 + head0];
    if (tid < 97) bs1 = gbias[(tid + 128) * 16 + head0];

    const uint32_t smb = smem_u32(SM);
    // single K B base; per-16-token group offset linear (+1280 B)
    const uint32_t bKb0 = smb + (uint32_t)((KH + ((((lane >> 4) & 1) << 3) + l7) * 20) << 2)
                        + (uint32_t)(((lane >> 3) & 1) << 4);

    const bool wh7 = (win_h == 7), ww7 = (win_w == 7);
    const bool hA4 = ((iA >> 3) >= 4), hB4 = ((iB >> 3) >= 4);
    const bool wA4 = ((iA & 7) >= 4),  wB4 = ((iB & 7) >= 4);
    const bool jw4 = (t4 >= 2);
    const int bA = 15 * (iA >> 3) + (iA & 7) + 112;
    const int bB = 15 * (iB >> 3) + (iB & 7) + 112;
    const int tokrow = l7 + (((lane >> 3) & 1) << 3);
    const int chanw  = (lane >> 4) << 2;
    const int ohA = ((win_h << 3) + (iA >> 3) + 4) & 63;
    const int owA = ((win_w << 3) + (iA & 7) + 4) & 63;
    const int ohB = ((win_h << 3) + (iB >> 3) + 4) & 63;
    const int owB = ((win_w << 3) + (iB & 7) + 4) & 63;
    const int dAb = ((((b << 6) + ohA) << 6) + owA) * 512 + (t4 << 1);
    const int dBb = ((((b << 6) + ohB) << 6) + owB) * 512 + (t4 << 1);

    for (int h = 0; h < 8; ++h) {
        const int head = head0 + h;

        // ---- Q direct load for CURRENT head (early issue; consumed after 2 syncs) ----
        const float* qA = gq + qbaseA + head * 32;
        const float* qB = gq + qbaseB + head * 32;
        float2 qa[4], qb[4];
        #pragma unroll
        for (int s = 0; s < 4; ++s) {
            qa[s] = *reinterpret_cast<const float2*>(qA + (s << 3));
            qb[s] = *reinterpret_cast<const float2*>(qB + (s << 3));
        }

        __syncthreads();   // previous iteration's smem readers done

        // ---- staged K/V fp16 -> smem ----
        #pragma unroll
        for (int r = 0; r < 4; ++r) {
            int u = tid + (r << 7);
            int t = u >> 3, cq = u & 7;
            int o20 = t * 20 + (cq << 1);
            *reinterpret_cast<uint2*>(&SM[KH + o20]) = khS[r];
            *reinterpret_cast<uint2*>(&SM[VP + o20]) = vS[r];
        }
        reinterpret_cast<float*>(SM)[BI + tid] = bs0;
        if (tid < 97) reinterpret_cast<float*>(SM)[BI + 128 + tid] = bs1;

        // ---- prefetch + convert next head's K/V (hidden under this head's compute) ----
        if (h < 7) {
            #pragma unroll
            for (int r = 0; r < 4; ++r) {
                int gb = tokbase[r] + (head + 1) * 32;
                float4 k = *reinterpret_cast<const float4*>(gk + gb);
                float4 v = *reinterpret_cast<const float4*>(gv + gb);
                khS[r] = make_uint2(packf16(k.x, k.y), packf16(k.z, k.w));
                vS[r]  = make_uint2(packf16(v.x, v.y), packf16(v.z, v.w));
            }
            bs0 = gbias[tid * 16 + head + 1];
            if (tid < 97) bs1 = gbias[(tid + 128) * 16 + head + 1];
        }
        __syncthreads();

        // ---- Q fragments in registers (hi/lo fp16 split) ----
        // frag index s: s=0 -> a0/a1 of kc0 (cols 2t4), s=1 -> a2/a3 of kc0 (cols 2t4+8),
        //               s=2,3 -> same for kc1 (cols +16)
        uint32_t qhA[4], qlA[4], qhB[4], qlB[4];
        #pragma unroll
        for (int s = 0; s < 4; ++s) {
            h2split(qa[s].x * scale, qa[s].y * scale, qhA[s], qlA[s]);
            h2split(qb[s].x * scale, qb[s].y * scale, qhB[s], qlB[s]);
        }

        // ---- QK: 2xFP16 (qh*k + ql*k), m16n8k16; A from regs, B via LDSM ----
        float c[8][4] = {};
        #pragma unroll
        for (int kc = 0; kc < 2; ++kc) {
            uint32_t ah[4], al[4];
            ah[0] = qhA[2 * kc];     ah[1] = qhB[2 * kc];
            ah[2] = qhA[2 * kc + 1]; ah[3] = qhB[2 * kc + 1];
            al[0] = qlA[2 * kc];     al[1] = qlB[2 * kc];
            al[2] = qlA[2 * kc + 1]; al[3] = qlB[2 * kc + 1];
            #pragma unroll
            for (int mm = 0; mm < 4; ++mm) {
                uint32_t bb[4];
                ldsm4(bb, bKb0 + (uint32_t)(mm * 1280) + (uint32_t)(kc << 5));
                float* c0 = c[2 * mm];
                float* c1 = c[2 * mm + 1];
                mma16(c0, ah, bb[0], bb[1]);
                mma16(c0, al, bb[0], bb[1]);
                mma16(c1, ah, bb[2], bb[3]);
                mma16(c1, al, bb[2], bb[3]);
            }
        }

        // ---- bias + analytic shift-mask + softmax ----
        const float* bias = reinterpret_cast<const float*>(SM) + BI;
        float mA = -1e30f, mB = -1e30f;
        #pragma unroll
        for (int nt = 0; nt < 8; ++nt) {
            const bool jh4 = (nt >= 4);
            const float subA = ((wh7 && (hA4 != jh4)) || (ww7 && (wA4 != jw4))) ? 100.0f : 0.0f;
            const float subB = ((wh7 && (hB4 != jh4)) || (ww7 && (wB4 != jw4))) ? 100.0f : 0.0f;
            #pragma unroll
            for (int q = 0; q < 2; ++q) {
                int bj = 15 * nt + (t4 << 1) + q;
                float xA = c[nt][q]     + bias[bA - bj] - subA;
                float xB = c[nt][2 + q] + bias[bB - bj] - subB;
                c[nt][q] = xA; c[nt][2 + q] = xB;
                mA = fmaxf(mA, xA); mB = fmaxf(mB, xB);
            }
        }
        mA = fmaxf(mA, __shfl_xor_sync(0xffffffffu, mA, 1));
        mA = fmaxf(mA, __shfl_xor_sync(0xffffffffu, mA, 2));
        mB = fmaxf(mB, __shfl_xor_sync(0xffffffffu, mB, 1));
        mB = fmaxf(mB, __shfl_xor_sync(0xffffffffu, mB, 2));
        float sA = 0.0f, sB = 0.0f;
        #pragma unroll
        for (int nt = 0; nt < 8; ++nt) {
            #pragma unroll
            for (int q = 0; q < 2; ++q) {
                float pA = __expf(c[nt][q] - mA);
                float pB = __expf(c[nt][2 + q] - mB);
                c[nt][q] = pA; c[nt][2 + q] = pB;
                sA += pA; sB += pB;
            }
        }
        sA += __shfl_xor_sync(0xffffffffu, sA, 1);
        sA += __shfl_xor_sync(0xffffffffu, sA, 2);
        sB += __shfl_xor_sync(0xffffffffu, sB, 1);
        sB += __shfl_xor_sync(0xffffffffu, sB, 2);
        const float invA = 1.0f / sA, invB = 1.0f / sB;

        // ---- PV: P in registers (acc frag == fp16 A frag); V via ldsm.trans ----
        float o[4][4] = {};
        #pragma unroll
        for (int ck = 0; ck < 4; ++ck) {
            uint32_t aF[4];
            aF[0] = packf16(c[2 * ck][0] * invA,     c[2 * ck][1] * invA);
            aF[1] = packf16(c[2 * ck][2] * invB,     c[2 * ck][3] * invB);
            aF[2] = packf16(c[2 * ck + 1][0] * invA, c[2 * ck + 1][1] * invA);
            aF[3] = packf16(c[2 * ck + 1][2] * invB, c[2 * ck + 1][3] * invB);
            uint32_t vrow = smb + (uint32_t)((VP + ((ck << 4) + tokrow) * 20 + chanw) << 2);
            #pragma unroll
            for (int nb = 0; nb < 2; ++nb) {
                uint32_t bv[4];
                ldsm4t(bv, vrow + (uint32_t)(nb << 5));
                mma16(o[2 * nb],     aF, bv[0], bv[1]);
                mma16(o[2 * nb + 1], aF, bv[2], bv[3]);
            }
        }

        // ---- store ----
        float* dA = gout + dAb + head * 32;
        float* dB = gout + dBb + head * 32;
        #pragma unroll
        for (int nt = 0; nt < 4; ++nt) {
            *reinterpret_cast<float2*>(dA + (nt << 3)) = make_float2(o[nt][0], o[nt][1]);
            *reinterpret_cast<float2*>(dB + (nt << 3)) = make_float2(o[nt][2], o[nt][3]);
        }
    }
}

}  // namespace

extern "C" void kernel_launch(void* const* d_in, const int* in_sizes, int n_in,
                              void* d_out, int out_size)
{
    (void)in_sizes; (void)n_in; (void)out_size;
    const float* q    = (const float*)d_in[0];
    const float* k    = (const float*)d_in[1];
    const float* v    = (const float*)d_in[2];
    const float* bias = (const float*)d_in[3];
    // 1024 windows x 2 head-octets = 2048 CTAs, 8 heads each
    swin_mma_kernel<<<2048, 128>>>(q, k, v, bias, (float*)d_out);
}